// round 15
// baseline (speedup 1.0000x reference)
#include <cuda_runtime.h>
#include <math.h>

#define BATCH 256
#define NSTEP 32
#define NIMG  (BATCH*NSTEP)

#define GUARD_BASE 81920
#define STATE_BASE 131072

#define IMG_STRIDE 30
#define S1_STRIDE  22
#define S1_PLANE   (13 * S1_STRIDE)

typedef unsigned long long u64t;

// packed f32x2 helpers (sm_103a FFMA2 path)
#define PACK2(d, lo, hi) \
    asm("mov.b64 %0, {%1, %2};" : "=l"(d) : "r"(__float_as_uint(lo)), "r"(__float_as_uint(hi)))
#define FMA2(d, a, b, c) \
    asm("fma.rn.f32x2 %0, %1, %2, %3;" : "=l"(d) : "l"(a), "l"(b), "l"(c))
#define UNPACK2(lo, hi, s) do { unsigned _ulo, _uhi; \
    asm("mov.b64 {%0, %1}, %2;" : "=r"(_ulo), "=r"(_uhi) : "l"(s)); \
    lo = __uint_as_float(_ulo); hi = __uint_as_float(_uhi); } while (0)

__device__ float g_M[600];                 // (6,10,10) transition matrices

struct SmemLayout {
    float img[2][28 * IMG_STRIDE];
    float s1p[2][8 * S1_PLANE];
    float s2[2][400];
    float s3[2][32];
    float w1p[8 * 12];  float b1[8];
    float w2pk[8 * 8 * 20];      // [ocpair][ic][k*2+half], padded to 20
    float b2[16];
    float w3pk[8 * 9 * 32 * 2];  // [icpair][k][oc] float2 (ic even, ic odd)
    float b3[32];
    float dwT[32 * 10]; float db[10];
    float logits[2][10]; float p2[2][10];
};

// ---------------------------------------------------------------------------
// Fused CNN, 2 images per CTA, 256 threads.
// Round-6 math; tid remapped so channel is innermost (warp-broadcast windows).
// ---------------------------------------------------------------------------
__global__ __launch_bounds__(256, 4) void cnn_kernel(
    const float* __restrict__ seq,
    const float* __restrict__ c1w, const float* __restrict__ c1b,
    const float* __restrict__ c2w, const float* __restrict__ c2b,
    const float* __restrict__ c3w, const float* __restrict__ c3b,
    const float* __restrict__ dw,  const float* __restrict__ db,
    const float* __restrict__ trans,
    float* __restrict__ out)
{
    extern __shared__ __align__(16) char smem_raw[];
    SmemLayout* S = (SmemLayout*)smem_raw;

    const int tid = threadIdx.x;

    // ---- prep (block 0): transition matrices into g_M ----
    if (blockIdx.x == 0 && tid < 60) {
        if (tid < 54) {
            const int r = tid / 9, i = tid - r * 9;
            const float* tp = trans + (r * 9 + i) * 10;
            float m = tp[0] * 10.f;
            #pragma unroll
            for (int j = 1; j < 10; j++) m = fmaxf(m, tp[j] * 10.f);
            float e[10];
            float s = 0.f;
            #pragma unroll
            for (int j = 0; j < 10; j++) { e[j] = __expf(tp[j] * 10.f - m); s += e[j]; }
            const float inv = 1.f / s;
            #pragma unroll
            for (int j = 0; j < 10; j++) g_M[r * 100 + i * 10 + j] = e[j] * inv;
        } else {
            const int r = tid - 54;
            #pragma unroll
            for (int j = 0; j < 10; j++) g_M[r * 100 + 90 + j] = (j == 9) ? 1.f : 0.f;
        }
    }

    // ---- stage inputs ----
    {
        const int img0 = blockIdx.x * 2;
        for (int k = tid; k < 784; k += 256) {
            const int im = k / 392, q = k - im * 392;
            const int img = img0 + im;
            const int n = img >> 8, b = img & 255;
            const float2 v = ((const float2*)(seq + ((long)b * NSTEP + n) * 784))[q];
            const int row = q / 14, col2 = q - row * 14;
            *(float2*)&S->img[im][row * IMG_STRIDE + col2 * 2] = v;
        }
    }
    if (tid < 8) {
        S->b1[tid] = c1b[tid];
        #pragma unroll
        for (int t = 0; t < 9; t++) S->w1p[tid * 12 + t] = c1w[tid * 9 + t];
    }
    if (tid < 128) {   // conv2 weights -> oc-pair packed
        const int oc = tid >> 3, ic = tid & 7;
        #pragma unroll
        for (int t = 0; t < 9; t++)
            S->w2pk[((oc >> 1) * 8 + ic) * 20 + t * 2 + (oc & 1)] = c2w[tid * 9 + t];
    }
    if (tid < 16) S->b2[tid] = c2b[tid];
    for (int k = tid; k < 512; k += 256) {   // conv3 weights -> ic-pair packed
        const int oc = k >> 4, ic = k & 15;
        #pragma unroll
        for (int t = 0; t < 9; t++)
            S->w3pk[(((ic >> 1) * 9 + t) * 32 + oc) * 2 + (ic & 1)] = c3w[k * 9 + t];
    }
    if (tid < 32) S->b3[tid] = c3b[tid];
    for (int k = tid; k < 320; k += 256)
        S->dwT[(k & 31) * 10 + (k >> 5)] = dw[k];
    if (tid < 10) S->db[tid] = db[tid];
    __syncthreads();

    // ---- Stage 1: conv1 + relu + pool. REMAP: c innermost (8 ch/warp share
    //      window addresses -> broadcast wavefronts). 208 threads ----
    if (tid < 208) {
        const int c  = tid & 7;          // channel: innermost -> warp-broadcast
        const int g  = tid >> 3;         // 0..25
        const int im = g / 13;
        const int y  = g - im * 13;
        {
            const float4 w0 = *(const float4*)&S->w1p[c * 12];
            const float4 w1 = *(const float4*)&S->w1p[c * 12 + 4];
            const float w8s = S->w1p[c * 12 + 8];
            const float ws[9] = {w0.x, w0.y, w0.z, w0.w, w1.x, w1.y, w1.z, w1.w, w8s};
            u64t W2[9];
            #pragma unroll
            for (int k = 0; k < 9; k++) PACK2(W2[k], ws[k], ws[k]);
            const float bias = S->b1[c];
            u64t B2; PACK2(B2, bias, bias);
            const int iy = 2 * y;

            float win[4][4];
            #pragma unroll
            for (int r = 0; r < 4; r++) {
                const float2 a = *(const float2*)&S->img[im][(iy + r) * IMG_STRIDE];
                const float2 d = *(const float2*)&S->img[im][(iy + r) * IMG_STRIDE + 2];
                win[r][0] = a.x; win[r][1] = a.y; win[r][2] = d.x; win[r][3] = d.y;
            }
            #pragma unroll
            for (int x = 0; x < 13; x++) {
                u64t a0 = B2, a1 = B2;
                #pragma unroll
                for (int ky = 0; ky < 3; ky++)
                    #pragma unroll
                    for (int kx = 0; kx < 3; kx++) {
                        u64t Pa, Pb;
                        PACK2(Pa, win[ky    ][kx], win[ky    ][kx + 1]);
                        PACK2(Pb, win[ky + 1][kx], win[ky + 1][kx + 1]);
                        FMA2(a0, Pa, W2[ky * 3 + kx], a0);
                        FMA2(a1, Pb, W2[ky * 3 + kx], a1);
                    }
                float v00, v01, v10, v11;
                UNPACK2(v00, v01, a0);
                UNPACK2(v10, v11, a1);
                S->s1p[im][c * S1_PLANE + y * S1_STRIDE + x] =
                    0.25f * (fmaxf(v00, 0.f) + fmaxf(v01, 0.f) +
                             fmaxf(v10, 0.f) + fmaxf(v11, 0.f));
                if (x < 12) {
                    #pragma unroll
                    for (int r = 0; r < 4; r++) {
                        win[r][0] = win[r][2]; win[r][1] = win[r][3];
                        const float2 nb = *(const float2*)
                            &S->img[im][(iy + r) * IMG_STRIDE + 2 * x + 4];
                        win[r][2] = nb.x; win[r][3] = nb.y;
                    }
                }
            }
        }
    }
    __syncthreads();

    // ---- Stage 2: conv2 + relu + pool. REMAP: ocg innermost (4 ocg/warp,
    //      8 positions/warp -> window addresses broadcast x4). 200 threads ----
    if (tid < 200) {
        const int ocg = tid & 3;         // oc-group: innermost -> broadcast
        const int q   = tid >> 2;        // 0..49
        const int im  = q / 25;
        const int pos = q - im * 25;
        const int y = pos / 5, x = pos - y * 5;
        const int iy = 2 * y, ix = 2 * x;
        const int op0 = ocg * 2, op1 = ocg * 2 + 1;

        u64t A[2][4];
        {
            u64t B0, B1;
            PACK2(B0, S->b2[ocg * 4 + 0], S->b2[ocg * 4 + 1]);
            PACK2(B1, S->b2[ocg * 4 + 2], S->b2[ocg * 4 + 3]);
            #pragma unroll
            for (int p = 0; p < 4; p++) { A[0][p] = B0; A[1][p] = B1; }
        }
        #pragma unroll
        for (int ic = 0; ic < 8; ic++) {
            float win[4][4];
            #pragma unroll
            for (int r = 0; r < 4; r++) {
                const float* rowp = &S->s1p[im][ic * S1_PLANE + (iy + r) * S1_STRIDE + ix];
                const float2 u = *(const float2*)rowp;
                const float2 v = *(const float2*)(rowp + 2);
                win[r][0] = u.x; win[r][1] = u.y; win[r][2] = v.x; win[r][3] = v.y;
            }
            const u64t* wq0 = (const u64t*)&S->w2pk[(op0 * 8 + ic) * 20];
            const u64t* wq1 = (const u64t*)&S->w2pk[(op1 * 8 + ic) * 20];
            #pragma unroll
            for (int ky = 0; ky < 3; ky++)
                #pragma unroll
                for (int kx = 0; kx < 3; kx++) {
                    const int k = ky * 3 + kx;
                    const u64t W0 = wq0[k], W1 = wq1[k];
                    u64t D00, D01, D10, D11;
                    PACK2(D00, win[ky    ][kx    ], win[ky    ][kx    ]);
                    PACK2(D01, win[ky    ][kx + 1], win[ky    ][kx + 1]);
                    PACK2(D10, win[ky + 1][kx    ], win[ky + 1][kx    ]);
                    PACK2(D11, win[ky + 1][kx + 1], win[ky + 1][kx + 1]);
                    FMA2(A[0][0], D00, W0, A[0][0]); FMA2(A[1][0], D00, W1, A[1][0]);
                    FMA2(A[0][1], D01, W0, A[0][1]); FMA2(A[1][1], D01, W1, A[1][1]);
                    FMA2(A[0][2], D10, W0, A[0][2]); FMA2(A[1][2], D10, W1, A[1][2]);
                    FMA2(A[0][3], D11, W0, A[0][3]); FMA2(A[1][3], D11, W1, A[1][3]);
                }
        }
        #pragma unroll
        for (int pr = 0; pr < 2; pr++) {
            float e0 = 0.f, e1 = 0.f;
            #pragma unroll
            for (int p = 0; p < 4; p++) {
                float lo, hi;
                UNPACK2(lo, hi, A[pr][p]);
                e0 += fmaxf(lo, 0.f);
                e1 += fmaxf(hi, 0.f);
            }
            S->s2[im][(ocg * 4 + 2 * pr    ) * 25 + pos] = 0.25f * e0;
            S->s2[im][(ocg * 4 + 2 * pr + 1) * 25 + pos] = 0.25f * e1;
        }
    }
    __syncthreads();

    // ---- Stage 3: conv3 + relu + pool. 256 threads (im,oc,pos), ic-pair FFMA2 ----
    {
        const int im  = tid >> 7;
        const int r3  = tid & 127;
        const int oc  = r3 >> 2;
        const int pos = r3 & 3;
        const int dy = pos >> 1, dx = pos & 1;

        u64t acc; PACK2(acc, 0.f, 0.f);
        #pragma unroll
        for (int icp = 0; icp < 8; icp++) {
            const float* pe = &S->s2[im][(2 * icp    ) * 25 + dy * 5 + dx];
            const float* po = &S->s2[im][(2 * icp + 1) * 25 + dy * 5 + dx];
            #pragma unroll
            for (int ky = 0; ky < 3; ky++)
                #pragma unroll
                for (int kx = 0; kx < 3; kx++) {
                    const int k = ky * 3 + kx;
                    const u64t W = *(const u64t*)&S->w3pk[((icp * 9 + k) * 32 + oc) * 2];
                    u64t D; PACK2(D, pe[ky * 5 + kx], po[ky * 5 + kx]);
                    FMA2(acc, D, W, acc);
                }
        }
        float lo, hi;
        UNPACK2(lo, hi, acc);
        float v = fmaxf(lo + hi + S->b3[oc], 0.f);
        v += __shfl_xor_sync(0xffffffffu, v, 1);
        v += __shfl_xor_sync(0xffffffffu, v, 2);
        if (pos == 0) S->s3[im][oc] = 0.25f * v;
    }
    __syncthreads();

    // ---- Dense + softmax + guards: warp 0 ----
    if (tid < 32) {
        if (tid < 20) {
            const int im = tid / 10, j = tid - im * 10;
            float v = S->db[j];
            #pragma unroll
            for (int k = 0; k < 32; k++) v += S->s3[im][k] * S->dwT[k * 10 + j];
            S->logits[im][j] = v;
        }
        __syncwarp();
        if (tid < 20) {
            const int im = tid / 10, j = tid - im * 10;
            float m = S->logits[im][0];
            #pragma unroll
            for (int k = 1; k < 10; k++) m = fmaxf(m, S->logits[im][k]);
            float sum = 0.f;
            #pragma unroll
            for (int k = 0; k < 10; k++) sum += __expf(S->logits[im][k] - m);
            const float p = __expf(S->logits[im][j] - m) / sum;
            S->p2[im][j] = p;
            out[(blockIdx.x * 2 + im) * 10 + j] = p;
        }
        __syncwarp();
        if (tid < 12) {
            const int im = tid / 6, j = tid - im * 6;
            const float* p = S->p2[im];
            float g;
            switch (j) {
                case 0:  g = p[8];         break;
                case 1:  g = p[4] + p[6];  break;
                case 2:  g = p[0] + p[2];  break;
                case 3:  g = p[7] + p[9];  break;
                case 4:  g = p[5];         break;
                default: g = p[1] + p[3];  break;
            }
            out[GUARD_BASE + (blockIdx.x * 2 + im) * 6 + j] = g;
        }
    }
}

// ---------------------------------------------------------------------------
// SFA: 32 blocks x 8 warps (round-6 proven version).
// ---------------------------------------------------------------------------
__global__ __launch_bounds__(256) void sfa_kernel(float* __restrict__ out)
{
    __shared__ float s_g[8][NSTEP * 6];

    const int tid  = threadIdx.x;
    const int w    = tid >> 5;
    const int lane = tid & 31;
    const int b    = blockIdx.x * 8 + w;

    const float* gbase = out + GUARD_BASE;
    #pragma unroll
    for (int k = lane; k < NSTEP * 6; k += 32) {
        const int n = k / 6, j = k - n * 6;
        s_g[w][k] = gbase[(n * BATCH + b) * 6 + j];
    }

    const int jj = (lane < 10) ? lane : 0;
    float Mr[6][10];
    #pragma unroll
    for (int r = 0; r < 6; r++)
        #pragma unroll
        for (int i = 0; i < 10; i++)
            Mr[r][i] = g_M[r * 100 + i * 10 + jj];
    __syncwarp();

    float st = (lane == 0) ? 1.f : 0.f;
    for (int n = 0; n < NSTEP; n++) {
        const float g0 = s_g[w][n*6+0], g1 = s_g[w][n*6+1], g2 = s_g[w][n*6+2];
        const float g3 = s_g[w][n*6+3], g4 = s_g[w][n*6+4], g5 = s_g[w][n*6+5];
        float a = 0.f;
        #pragma unroll
        for (int i = 0; i < 10; i++) {
            const float si = __shfl_sync(0xffffffff, st, i);
            const float mij = g0 * Mr[0][i] + g1 * Mr[1][i] + g2 * Mr[2][i]
                            + g3 * Mr[3][i] + g4 * Mr[4][i] + g5 * Mr[5][i];
            a += si * mij;
        }
        st = a;
    }
    if (lane < 10) out[STATE_BASE + b * 10 + lane] = st;
}

// ---------------------------------------------------------------------------
extern "C" void kernel_launch(void* const* d_in, const int* in_sizes, int n_in,
                              void* d_out, int out_size)
{
    const float* seq   = (const float*)d_in[0];
    const float* c1w   = (const float*)d_in[1];
    const float* c1b   = (const float*)d_in[2];
    const float* c2w   = (const float*)d_in[3];
    const float* c2b   = (const float*)d_in[4];
    const float* c3w   = (const float*)d_in[5];
    const float* c3b   = (const float*)d_in[6];
    const float* dw    = (const float*)d_in[7];
    const float* db    = (const float*)d_in[8];
    const float* trans = (const float*)d_in[9];
    float* out = (float*)d_out;

    const int smem_bytes = (int)sizeof(SmemLayout);
    cudaFuncSetAttribute(cnn_kernel, cudaFuncAttributeMaxDynamicSharedMemorySize,
                         smem_bytes);

    cnn_kernel<<<NIMG / 2, 256, smem_bytes>>>(seq, c1w, c1b, c2w, c2b,
                                              c3w, c3b, dw, db, trans, out);
    sfa_kernel<<<BATCH / 8, 256>>>(out);
}

// round 16
// speedup vs baseline: 1.3861x; 1.3861x over previous
#include <cuda_runtime.h>
#include <math.h>

#define BATCH 256
#define NSTEP 32
#define NIMG  (BATCH*NSTEP)

#define GUARD_BASE 81920
#define STATE_BASE 131072

#define IMG_STRIDE 30
#define S1_STRIDE  22
#define S1_PLANE   (13 * S1_STRIDE)

typedef unsigned long long u64t;

// packed f32x2 helpers (sm_103a FFMA2 path)
#define PACK2(d, lo, hi) \
    asm("mov.b64 %0, {%1, %2};" : "=l"(d) : "r"(__float_as_uint(lo)), "r"(__float_as_uint(hi)))
#define FMA2(d, a, b, c) \
    asm("fma.rn.f32x2 %0, %1, %2, %3;" : "=l"(d) : "l"(a), "l"(b), "l"(c))
#define UNPACK2(lo, hi, s) do { unsigned _ulo, _uhi; \
    asm("mov.b64 {%0, %1}, %2;" : "=r"(_ulo), "=r"(_uhi) : "l"(s)); \
    lo = __uint_as_float(_ulo); hi = __uint_as_float(_uhi); } while (0)

__device__ float g_M[600];                 // (6,10,10) transition matrices
__device__ float g_guardT[BATCH][NSTEP*6]; // transposed guards for sfa

struct SmemLayout {
    float img[2][28 * IMG_STRIDE];
    float s1p[2][8 * S1_PLANE];
    float s2[2][400];
    float s3[2][32];
    float w1p[8 * 12];  float b1[8];
    float w2pk[8 * 8 * 20];      // [ocpair][ic][k*2+half], padded to 20
    float b2[16];
    float w3pk[8 * 9 * 32 * 2];  // [icpair][k][oc] float2 (ic even, ic odd)
    float b3[32];
    float dwT[32 * 10]; float db[10];
    float logits[2][10]; float p2[2][10];
};

// ---------------------------------------------------------------------------
// Fused CNN, 2 images per CTA, 256 threads (round-6 proven configuration).
// ---------------------------------------------------------------------------
__global__ __launch_bounds__(256, 4) void cnn_kernel(
    const float* __restrict__ seq,
    const float* __restrict__ c1w, const float* __restrict__ c1b,
    const float* __restrict__ c2w, const float* __restrict__ c2b,
    const float* __restrict__ c3w, const float* __restrict__ c3b,
    const float* __restrict__ dw,  const float* __restrict__ db,
    const float* __restrict__ trans,
    float* __restrict__ out)
{
    extern __shared__ __align__(16) char smem_raw[];
    SmemLayout* S = (SmemLayout*)smem_raw;

    const int tid = threadIdx.x;

    // ---- prep (block 0): transition matrices into g_M ----
    if (blockIdx.x == 0 && tid < 60) {
        if (tid < 54) {
            const int r = tid / 9, i = tid - r * 9;
            const float* tp = trans + (r * 9 + i) * 10;
            float m = tp[0] * 10.f;
            #pragma unroll
            for (int j = 1; j < 10; j++) m = fmaxf(m, tp[j] * 10.f);
            float e[10];
            float s = 0.f;
            #pragma unroll
            for (int j = 0; j < 10; j++) { e[j] = __expf(tp[j] * 10.f - m); s += e[j]; }
            const float inv = 1.f / s;
            #pragma unroll
            for (int j = 0; j < 10; j++) g_M[r * 100 + i * 10 + j] = e[j] * inv;
        } else {
            const int r = tid - 54;
            #pragma unroll
            for (int j = 0; j < 10; j++) g_M[r * 100 + 90 + j] = (j == 9) ? 1.f : 0.f;
        }
    }

    // ---- stage inputs ----
    {
        const int img0 = blockIdx.x * 2;
        for (int k = tid; k < 784; k += 256) {
            const int im = k / 392, q = k - im * 392;
            const int img = img0 + im;
            const int n = img >> 8, b = img & 255;
            const float2 v = ((const float2*)(seq + ((long)b * NSTEP + n) * 784))[q];
            const int row = q / 14, col2 = q - row * 14;
            *(float2*)&S->img[im][row * IMG_STRIDE + col2 * 2] = v;
        }
    }
    if (tid < 8) {
        S->b1[tid] = c1b[tid];
        #pragma unroll
        for (int t = 0; t < 9; t++) S->w1p[tid * 12 + t] = c1w[tid * 9 + t];
    }
    if (tid < 128) {   // conv2 weights -> oc-pair packed
        const int oc = tid >> 3, ic = tid & 7;
        #pragma unroll
        for (int t = 0; t < 9; t++)
            S->w2pk[((oc >> 1) * 8 + ic) * 20 + t * 2 + (oc & 1)] = c2w[tid * 9 + t];
    }
    if (tid < 16) S->b2[tid] = c2b[tid];
    for (int k = tid; k < 512; k += 256) {   // conv3 weights -> ic-pair packed
        const int oc = k >> 4, ic = k & 15;
        #pragma unroll
        for (int t = 0; t < 9; t++)
            S->w3pk[(((ic >> 1) * 9 + t) * 32 + oc) * 2 + (ic & 1)] = c3w[k * 9 + t];
    }
    if (tid < 32) S->b3[tid] = c3b[tid];
    for (int k = tid; k < 320; k += 256)
        S->dwT[(k & 31) * 10 + (k >> 5)] = dw[k];
    if (tid < 10) S->db[tid] = db[tid];
    __syncthreads();

    // ---- Stage 1: conv1 + relu + pool (FFMA2 packed along pool-dx) ----
    {
        const int g  = tid >> 4;
        const int y  = tid & 15;
        const int im = g >> 3;
        const int c  = g & 7;
        if (y < 13) {
            const float4 w0 = *(const float4*)&S->w1p[c * 12];
            const float4 w1 = *(const float4*)&S->w1p[c * 12 + 4];
            const float w8s = S->w1p[c * 12 + 8];
            const float ws[9] = {w0.x, w0.y, w0.z, w0.w, w1.x, w1.y, w1.z, w1.w, w8s};
            u64t W2[9];
            #pragma unroll
            for (int k = 0; k < 9; k++) PACK2(W2[k], ws[k], ws[k]);
            const float bias = S->b1[c];
            u64t B2; PACK2(B2, bias, bias);
            const int iy = 2 * y;

            float win[4][4];
            #pragma unroll
            for (int r = 0; r < 4; r++) {
                const float2 a = *(const float2*)&S->img[im][(iy + r) * IMG_STRIDE];
                const float2 d = *(const float2*)&S->img[im][(iy + r) * IMG_STRIDE + 2];
                win[r][0] = a.x; win[r][1] = a.y; win[r][2] = d.x; win[r][3] = d.y;
            }
            #pragma unroll
            for (int x = 0; x < 13; x++) {
                u64t a0 = B2, a1 = B2;
                #pragma unroll
                for (int ky = 0; ky < 3; ky++)
                    #pragma unroll
                    for (int kx = 0; kx < 3; kx++) {
                        u64t Pa, Pb;
                        PACK2(Pa, win[ky    ][kx], win[ky    ][kx + 1]);
                        PACK2(Pb, win[ky + 1][kx], win[ky + 1][kx + 1]);
                        FMA2(a0, Pa, W2[ky * 3 + kx], a0);
                        FMA2(a1, Pb, W2[ky * 3 + kx], a1);
                    }
                float v00, v01, v10, v11;
                UNPACK2(v00, v01, a0);
                UNPACK2(v10, v11, a1);
                S->s1p[im][c * S1_PLANE + y * S1_STRIDE + x] =
                    0.25f * (fmaxf(v00, 0.f) + fmaxf(v01, 0.f) +
                             fmaxf(v10, 0.f) + fmaxf(v11, 0.f));
                if (x < 12) {
                    #pragma unroll
                    for (int r = 0; r < 4; r++) {
                        win[r][0] = win[r][2]; win[r][1] = win[r][3];
                        const float2 nb = *(const float2*)
                            &S->img[im][(iy + r) * IMG_STRIDE + 2 * x + 4];
                        win[r][2] = nb.x; win[r][3] = nb.y;
                    }
                }
            }
        }
    }
    __syncthreads();

    // ---- Stage 2: conv2 + relu + pool (FFMA2 packed along oc-pairs) ----
    if (tid < 200) {
        const int im  = tid / 100;
        const int r2  = tid - im * 100;
        const int ocg = r2 / 25;
        const int pos = r2 - ocg * 25;
        const int y = pos / 5, x = pos - y * 5;
        const int iy = 2 * y, ix = 2 * x;
        const int op0 = ocg * 2, op1 = ocg * 2 + 1;

        u64t A[2][4];
        {
            u64t B0, B1;
            PACK2(B0, S->b2[ocg * 4 + 0], S->b2[ocg * 4 + 1]);
            PACK2(B1, S->b2[ocg * 4 + 2], S->b2[ocg * 4 + 3]);
            #pragma unroll
            for (int p = 0; p < 4; p++) { A[0][p] = B0; A[1][p] = B1; }
        }
        #pragma unroll
        for (int ic = 0; ic < 8; ic++) {
            float win[4][4];
            #pragma unroll
            for (int r = 0; r < 4; r++) {
                const float* rowp = &S->s1p[im][ic * S1_PLANE + (iy + r) * S1_STRIDE + ix];
                const float2 u = *(const float2*)rowp;
                const float2 v = *(const float2*)(rowp + 2);
                win[r][0] = u.x; win[r][1] = u.y; win[r][2] = v.x; win[r][3] = v.y;
            }
            const u64t* wq0 = (const u64t*)&S->w2pk[(op0 * 8 + ic) * 20];
            const u64t* wq1 = (const u64t*)&S->w2pk[(op1 * 8 + ic) * 20];
            #pragma unroll
            for (int ky = 0; ky < 3; ky++)
                #pragma unroll
                for (int kx = 0; kx < 3; kx++) {
                    const int k = ky * 3 + kx;
                    const u64t W0 = wq0[k], W1 = wq1[k];
                    u64t D00, D01, D10, D11;
                    PACK2(D00, win[ky    ][kx    ], win[ky    ][kx    ]);
                    PACK2(D01, win[ky    ][kx + 1], win[ky    ][kx + 1]);
                    PACK2(D10, win[ky + 1][kx    ], win[ky + 1][kx    ]);
                    PACK2(D11, win[ky + 1][kx + 1], win[ky + 1][kx + 1]);
                    FMA2(A[0][0], D00, W0, A[0][0]); FMA2(A[1][0], D00, W1, A[1][0]);
                    FMA2(A[0][1], D01, W0, A[0][1]); FMA2(A[1][1], D01, W1, A[1][1]);
                    FMA2(A[0][2], D10, W0, A[0][2]); FMA2(A[1][2], D10, W1, A[1][2]);
                    FMA2(A[0][3], D11, W0, A[0][3]); FMA2(A[1][3], D11, W1, A[1][3]);
                }
        }
        #pragma unroll
        for (int pr = 0; pr < 2; pr++) {
            float e0 = 0.f, e1 = 0.f;
            #pragma unroll
            for (int p = 0; p < 4; p++) {
                float lo, hi;
                UNPACK2(lo, hi, A[pr][p]);
                e0 += fmaxf(lo, 0.f);
                e1 += fmaxf(hi, 0.f);
            }
            S->s2[im][(ocg * 4 + 2 * pr    ) * 25 + pos] = 0.25f * e0;
            S->s2[im][(ocg * 4 + 2 * pr + 1) * 25 + pos] = 0.25f * e1;
        }
    }
    __syncthreads();

    // ---- Stage 3: conv3 + relu + pool. 256 threads (im,oc,pos), ic-pair FFMA2 ----
    {
        const int im  = tid >> 7;
        const int r3  = tid & 127;
        const int oc  = r3 >> 2;
        const int pos = r3 & 3;
        const int dy = pos >> 1, dx = pos & 1;

        u64t acc; PACK2(acc, 0.f, 0.f);
        #pragma unroll
        for (int icp = 0; icp < 8; icp++) {
            const float* pe = &S->s2[im][(2 * icp    ) * 25 + dy * 5 + dx];
            const float* po = &S->s2[im][(2 * icp + 1) * 25 + dy * 5 + dx];
            #pragma unroll
            for (int ky = 0; ky < 3; ky++)
                #pragma unroll
                for (int kx = 0; kx < 3; kx++) {
                    const int k = ky * 3 + kx;
                    const u64t W = *(const u64t*)&S->w3pk[((icp * 9 + k) * 32 + oc) * 2];
                    u64t D; PACK2(D, pe[ky * 5 + kx], po[ky * 5 + kx]);
                    FMA2(acc, D, W, acc);
                }
        }
        float lo, hi;
        UNPACK2(lo, hi, acc);
        float v = fmaxf(lo + hi + S->b3[oc], 0.f);
        v += __shfl_xor_sync(0xffffffffu, v, 1);
        v += __shfl_xor_sync(0xffffffffu, v, 2);
        if (pos == 0) S->s3[im][oc] = 0.25f * v;
    }
    __syncthreads();

    // ---- Dense + softmax + guards: warp 0 ----
    if (tid < 32) {
        if (tid < 20) {
            const int im = tid / 10, j = tid - im * 10;
            float v = S->db[j];
            #pragma unroll
            for (int k = 0; k < 32; k++) v += S->s3[im][k] * S->dwT[k * 10 + j];
            S->logits[im][j] = v;
        }
        __syncwarp();
        if (tid < 20) {
            const int im = tid / 10, j = tid - im * 10;
            float m = S->logits[im][0];
            #pragma unroll
            for (int k = 1; k < 10; k++) m = fmaxf(m, S->logits[im][k]);
            float sum = 0.f;
            #pragma unroll
            for (int k = 0; k < 10; k++) sum += __expf(S->logits[im][k] - m);
            const float p = __expf(S->logits[im][j] - m) / sum;
            S->p2[im][j] = p;
            out[(blockIdx.x * 2 + im) * 10 + j] = p;
        }
        __syncwarp();
        if (tid < 12) {
            const int im = tid / 6, j = tid - im * 6;
            const float* p = S->p2[im];
            float g;
            switch (j) {
                case 0:  g = p[8];         break;
                case 1:  g = p[4] + p[6];  break;
                case 2:  g = p[0] + p[2];  break;
                case 3:  g = p[7] + p[9];  break;
                case 4:  g = p[5];         break;
                default: g = p[1] + p[3];  break;
            }
            const int img = blockIdx.x * 2 + im;
            out[GUARD_BASE + img * 6 + j] = g;
            g_guardT[img & 255][(img >> 8) * 6 + j] = g;   // transposed copy
        }
    }
}

// ---------------------------------------------------------------------------
// SFA: 32 blocks x 8 warps; warp handles one batch element, coalesced guards.
// ---------------------------------------------------------------------------
__global__ __launch_bounds__(256) void sfa_kernel(float* __restrict__ out)
{
    __shared__ float s_g[8][NSTEP * 6];

    const int tid  = threadIdx.x;
    const int w    = tid >> 5;
    const int lane = tid & 31;
    const int b    = blockIdx.x * 8 + w;

    #pragma unroll
    for (int k = lane; k < NSTEP * 6; k += 32)
        s_g[w][k] = g_guardT[b][k];

    const int jj = (lane < 10) ? lane : 0;
    float Mr[6][10];
    #pragma unroll
    for (int r = 0; r < 6; r++)
        #pragma unroll
        for (int i = 0; i < 10; i++)
            Mr[r][i] = g_M[r * 100 + i * 10 + jj];
    __syncwarp();

    float st = (lane == 0) ? 1.f : 0.f;
    for (int n = 0; n < NSTEP; n++) {
        const float g0 = s_g[w][n*6+0], g1 = s_g[w][n*6+1], g2 = s_g[w][n*6+2];
        const float g3 = s_g[w][n*6+3], g4 = s_g[w][n*6+4], g5 = s_g[w][n*6+5];
        float a = 0.f;
        #pragma unroll
        for (int i = 0; i < 10; i++) {
            const float si = __shfl_sync(0xffffffff, st, i);
            const float mij = g0 * Mr[0][i] + g1 * Mr[1][i] + g2 * Mr[2][i]
                            + g3 * Mr[3][i] + g4 * Mr[4][i] + g5 * Mr[5][i];
            a += si * mij;
        }
        st = a;
    }
    if (lane < 10) out[STATE_BASE + b * 10 + lane] = st;
}

// ---------------------------------------------------------------------------
extern "C" void kernel_launch(void* const* d_in, const int* in_sizes, int n_in,
                              void* d_out, int out_size)
{
    const float* seq   = (const float*)d_in[0];
    const float* c1w   = (const float*)d_in[1];
    const float* c1b   = (const float*)d_in[2];
    const float* c2w   = (const float*)d_in[3];
    const float* c2b   = (const float*)d_in[4];
    const float* c3w   = (const float*)d_in[5];
    const float* c3b   = (const float*)d_in[6];
    const float* dw    = (const float*)d_in[7];
    const float* db    = (const float*)d_in[8];
    const float* trans = (const float*)d_in[9];
    float* out = (float*)d_out;

    const int smem_bytes = (int)sizeof(SmemLayout);
    cudaFuncSetAttribute(cnn_kernel, cudaFuncAttributeMaxDynamicSharedMemorySize,
                         smem_bytes);

    cnn_kernel<<<NIMG / 2, 256, smem_bytes>>>(seq, c1w, c1b, c2w, c2b,
                                              c3w, c3b, dw, db, trans, out);
    sfa_kernel<<<BATCH / 8, 256>>>(out);
}